// round 16
// baseline (speedup 1.0000x reference)
#include <cuda_runtime.h>
#include <cuda_fp16.h>
#include <math.h>
#include <stdint.h>

// ---------------------------------------------------------------- constants
#define IN_DIM  128
#define OUT_DIM 256
#define NUM_F   8
#define BATCH   1024
#define KF      9
#define KDIM    1152                 // 128*9

#define TILE_M  64
#define TILE_N  128
#define BK      64                   // fp16 elems per k-chunk (128B rows)
// z chunks: z0 [0,5) z1 [5,10) z2 [10,14) z3 [14,18)
// stage buffer: A 8KB @0, W 16KB @8192  -> 24KB
#define STAGE_BYTES 24576
#define SMEM_BYTES  (5 * STAGE_BYTES)   // 122880 (max 5 chunks)

// ---------------------------------------------------------------- scratch
__device__ __align__(16) __half g_A[BATCH * KDIM];
__device__ __align__(16) __half g_W[OUT_DIM * KDIM];

// ---------------------------------------------------------------- helpers
__device__ __forceinline__ uint32_t smem_u32(const void* p) {
    uint32_t a;
    asm("{ .reg .u64 t; cvta.to.shared.u64 t, %1; cvt.u32.u64 %0, t; }" : "=r"(a) : "l"(p));
    return a;
}
#define CP_ASYNC16(dst, src) \
    asm volatile("cp.async.cg.shared.global [%0], [%1], 16;" :: "r"(dst), "l"(src))
#define CP_COMMIT() asm volatile("cp.async.commit_group;" ::: "memory")
#define CP_WAIT(n)  asm volatile("cp.async.wait_group %0;" :: "n"(n) : "memory")

#define LDSM_X4(r, addr)                                                      \
    asm volatile("ldmatrix.sync.aligned.m8n8.x4.shared.b16 {%0,%1,%2,%3}, [%4];" \
                 : "=r"((r)[0]), "=r"((r)[1]), "=r"((r)[2]), "=r"((r)[3]) : "r"(addr))

#define MMA16816F16(c, a, b0, b1)                                             \
    asm volatile("mma.sync.aligned.m16n8k16.row.col.f32.f16.f16.f32 "         \
                 "{%0,%1,%2,%3}, {%4,%5,%6,%7}, {%8,%9}, {%0,%1,%2,%3};"      \
                 : "+f"((c)[0]), "+f"((c)[1]), "+f"((c)[2]), "+f"((c)[3])     \
                 : "r"((a)[0]), "r"((a)[1]), "r"((a)[2]), "r"((a)[3]),        \
                   "r"(b0), "r"(b1))

// ---------------------------------------------------------------- fused prep
// blocks [0,128):    W pack -> fp16 (2 o-rows per block, smem staged)
// blocks [128,640):  A features -> fp16 (2 b-rows per block, smem staged)
// blocks [640,896):  out = bias (float4)
__global__ void prep_kernel(const float* __restrict__ x,
                            const float* __restrict__ grid,
                            const float* __restrict__ coef,
                            const float* __restrict__ scale_sp,
                            const float* __restrict__ scale_base,
                            const float* __restrict__ bias_w,
                            float* __restrict__ out) {
    __shared__ __align__(16) __half sh[2 * KDIM];   // 4608B

    const int blk = blockIdx.x;
    const int tid = threadIdx.x;

    if (blk >= 640) {                        // bias init
        int idx = (blk - 640) * 256 + tid;   // float4 units
        float4 v = reinterpret_cast<const float4*>(bias_w)[idx & 63];
        reinterpret_cast<float4*>(out)[idx] = v;
        return;
    }

    float vals[KF];
    __half* gdst;

    if (blk < 128) {                         // ---- W pack (fp16)
        int n = blk * 256 + tid;             // o*128 + i
        float sp = scale_sp[n];
        float4 c0 = reinterpret_cast<const float4*>(coef + (size_t)n * NUM_F)[0];
        float4 c1 = reinterpret_cast<const float4*>(coef + (size_t)n * NUM_F)[1];
        vals[0] = c0.x * sp; vals[1] = c0.y * sp; vals[2] = c0.z * sp; vals[3] = c0.w * sp;
        vals[4] = c1.x * sp; vals[5] = c1.y * sp; vals[6] = c1.z * sp; vals[7] = c1.w * sp;
        vals[8] = scale_base[n];
        gdst = g_W + (size_t)blk * 2 * KDIM;
    } else {                                 // ---- A features
        int idx = (blk - 128) * 256 + tid;   // b*128 + i
        float xv = x[idx];
        // sin(k*x), k=1..8 via Chebyshev recurrence: 2 MUFU instead of 8
        float s1  = __sinf(xv);
        float c1v = __cosf(xv);
        float two_c = 2.0f * c1v;
        float sm1 = 0.0f, sk = s1;
        vals[0] = s1;
        #pragma unroll
        for (int f = 1; f < NUM_F; f++) {
            float sn = two_c * sk - sm1;
            vals[f] = sn;
            sm1 = sk;
            sk = sn;
        }
        vals[NUM_F] = xv * (1.0f / (1.0f + __expf(-xv)));   // silu
        gdst = g_A + (size_t)(blk - 128) * 2 * KDIM;
    }

    // stage into smem (local row = tid>>7, col = (tid&127)*9), coalesced flush
    {
        int lofs = (tid >> 7) * KDIM + (tid & 127) * KF;
        #pragma unroll
        for (int f = 0; f < KF; f++) sh[lofs + f] = __float2half(vals[f]);
    }
    __syncthreads();
    for (int u = tid; u < 288; u += 256)
        reinterpret_cast<uint4*>(gdst)[u] = reinterpret_cast<const uint4*>(sh)[u];
}

// ---------------------------------------------------------------- GEMM
// grid (16, 2, 4) = 128 CTAs = ONE WAVE.  256 threads, 8 warps (2x4),
// warp tile 32x32 with 8 independent MMAs per kstep (proven best ILP shape).
// PREFETCH-ALL: every k-chunk's cp.async group is issued up front; the
// mainloop only waits/computes (compile-time wait counts, no mid-loop issue).
// z-chunks 5/5/4/4.  Epilogue RED.ADD into out (bias prewritten by prep).
__global__ __launch_bounds__(256) void gemm_kernel(float* __restrict__ out) {
    extern __shared__ __align__(128) uint8_t smem[];

    const int tid = threadIdx.x;
    const int wid = tid >> 5;
    const int lid = tid & 31;
    const int wm  = wid >> 2;          // 0..1 -> m rows wm*32
    const int wn  = wid & 3;           // 0..3 -> n cols wn*32
    const int m0  = blockIdx.x * TILE_M;
    const int n0  = blockIdx.y * TILE_N;
    const int z   = blockIdx.z;

    const int c0     = (z < 2) ? z * 5 : 10 + (z - 2) * 4;
    const int scount = (z < 2) ? 5 : 4;

    const uint32_t smbase = smem_u32(smem);

    // ldmatrix addressing (proven pattern, warp tile 32x32)
    const uint32_t swz   = (uint32_t)((lid & 7) * 16);
    const uint32_t acol  = (uint32_t)((lid >> 4) * 16);
    const uint32_t arow0 = (uint32_t)((wm * 32 + (lid & 15)) * 128);
    const uint32_t arow1 = arow0 + 16 * 128;
    const uint32_t bcol  = (uint32_t)(((lid >> 3) & 1) * 16);
    const uint32_t brow0 = (uint32_t)((wn * 32 + (lid >> 4) * 8 + (lid & 7)) * 128);
    const uint32_t brow1 = brow0 + 16 * 128;

    float acc[2][4][4];
    #pragma unroll
    for (int j = 0; j < 2; j++)
        #pragma unroll
        for (int q = 0; q < 4; q++)
            #pragma unroll
            for (int r = 0; r < 4; r++) acc[j][q][r] = 0.0f;

    // loader: per stage 1536 x 16B -> 6 cp.async per thread
    const int lrow = tid >> 3;                       // 0..31
    const int lc16 = tid & 7;
    const uint32_t lswz = (uint32_t)((lc16 * 16) ^ ((lrow & 7) * 16));

    auto issue_stage = [&](int s) {
        const int kofs = (c0 + s) * BK + lc16 * 8;
        const uint32_t sb = smbase + s * STAGE_BYTES;
        const uint32_t rb = (uint32_t)(lrow * 128) + lswz;
        CP_ASYNC16(sb + rb,                 g_A + (size_t)(m0 + lrow) * KDIM + kofs);
        CP_ASYNC16(sb + rb + 32 * 128,      g_A + (size_t)(m0 + lrow + 32) * KDIM + kofs);
        CP_ASYNC16(sb + 8192 + rb,          g_W + (size_t)(n0 + lrow) * KDIM + kofs);
        CP_ASYNC16(sb + 8192 + rb + 4096,   g_W + (size_t)(n0 + lrow + 32) * KDIM + kofs);
        CP_ASYNC16(sb + 8192 + rb + 8192,   g_W + (size_t)(n0 + lrow + 64) * KDIM + kofs);
        CP_ASYNC16(sb + 8192 + rb + 12288,  g_W + (size_t)(n0 + lrow + 96) * KDIM + kofs);
        CP_COMMIT();
    };

    // issue ALL stages up front
    for (int s = 0; s < scount; s++) issue_stage(s);

    auto compute_chunk = [&](int s) {
        const uint32_t sb  = smbase + s * STAGE_BYTES;
        const uint32_t sbW = sb + 8192;
        #pragma unroll
        for (int kb2 = 0; kb2 < 128; kb2 += 32) {     // 4 k16 steps (bytes)
            const uint32_t ka = ((uint32_t)kb2 + acol) ^ swz;
            const uint32_t kb = ((uint32_t)kb2 + bcol) ^ swz;
            uint32_t a0[4], a1[4], w0[4], w1[4];
            LDSM_X4(a0, sb + arow0 + ka);
            LDSM_X4(a1, sb + arow1 + ka);
            LDSM_X4(w0, sbW + brow0 + kb);
            LDSM_X4(w1, sbW + brow1 + kb);
            // 8 independent MMAs
            MMA16816F16(acc[0][0], a0, w0[0], w0[1]);
            MMA16816F16(acc[0][1], a0, w0[2], w0[3]);
            MMA16816F16(acc[0][2], a0, w1[0], w1[1]);
            MMA16816F16(acc[0][3], a0, w1[2], w1[3]);
            MMA16816F16(acc[1][0], a1, w0[0], w0[1]);
            MMA16816F16(acc[1][1], a1, w0[2], w0[3]);
            MMA16816F16(acc[1][2], a1, w1[0], w1[1]);
            MMA16816F16(acc[1][3], a1, w1[2], w1[3]);
        }
    };

    // drain with compile-time wait counts (groups complete in commit order)
    if (scount == 5) {
        CP_WAIT(4); __syncthreads(); compute_chunk(0);
        CP_WAIT(3); __syncthreads(); compute_chunk(1);
        CP_WAIT(2); __syncthreads(); compute_chunk(2);
        CP_WAIT(1); __syncthreads(); compute_chunk(3);
        CP_WAIT(0); __syncthreads(); compute_chunk(4);
    } else {
        CP_WAIT(3); __syncthreads(); compute_chunk(0);
        CP_WAIT(2); __syncthreads(); compute_chunk(1);
        CP_WAIT(1); __syncthreads(); compute_chunk(2);
        CP_WAIT(0); __syncthreads(); compute_chunk(3);
    }

    // epilogue: RED.ADD into out (bias already written by prep)
    #pragma unroll
    for (int j = 0; j < 2; j++) {
        int r = m0 + wm * 32 + j * 16 + (lid >> 2);
        #pragma unroll
        for (int q = 0; q < 4; q++) {
            int c = n0 + wn * 32 + q * 8 + (lid & 3) * 2;
            float* p = out + (size_t)r * OUT_DIM + c;
            atomicAdd(p,                    acc[j][q][0]);
            atomicAdd(p + 1,                acc[j][q][1]);
            atomicAdd(p + 8 * OUT_DIM,      acc[j][q][2]);
            atomicAdd(p + 8 * OUT_DIM + 1,  acc[j][q][3]);
        }
    }
}

// ---------------------------------------------------------------- launch
extern "C" void kernel_launch(void* const* d_in, const int* in_sizes, int n_in,
                              void* d_out, int out_size) {
    const float* x          = (const float*)d_in[0];
    const float* grid       = (const float*)d_in[1];
    const float* coef       = (const float*)d_in[2];
    const float* scale_sp   = (const float*)d_in[3];
    const float* scale_base = (const float*)d_in[4];
    const float* bias_w     = (const float*)d_in[5];
    float* out = (float*)d_out;

    cudaFuncSetAttribute(gemm_kernel, cudaFuncAttributeMaxDynamicSharedMemorySize,
                         SMEM_BYTES);

    prep_kernel<<<896, 256>>>(x, grid, coef, scale_sp, scale_base, bias_w, out);

    dim3 gdim(BATCH / TILE_M, OUT_DIM / TILE_N, 4);   // (16, 2, 4) = 128 CTAs
    gemm_kernel<<<gdim, 256, SMEM_BYTES>>>(out);
}

// round 17
// speedup vs baseline: 1.5015x; 1.5015x over previous
#include <cuda_runtime.h>
#include <cuda_fp16.h>
#include <math.h>
#include <stdint.h>

// ---------------------------------------------------------------- constants
#define IN_DIM  128
#define OUT_DIM 256
#define NUM_F   8
#define BATCH   1024
#define KF      9
#define KDIM    1152                 // 128*9

#define TILE_M  64
#define TILE_N  64
#define BK      64                   // fp16 elems per k-chunk (128B rows)
#define ZSPLIT  5                    // chunks 4/4/4/3/3
// stage buffer: A 8KB @0, W 8KB @8192 -> 16KB; max 4 stages resident
#define STAGE_BYTES 16384
#define SMEM_BYTES  (4 * STAGE_BYTES)   // 65536  (stays under 100KB carveout)

// ---------------------------------------------------------------- scratch
__device__ __align__(16) __half g_A[BATCH * KDIM];
__device__ __align__(16) __half g_W[OUT_DIM * KDIM];

// ---------------------------------------------------------------- helpers
__device__ __forceinline__ uint32_t smem_u32(const void* p) {
    uint32_t a;
    asm("{ .reg .u64 t; cvta.to.shared.u64 t, %1; cvt.u32.u64 %0, t; }" : "=r"(a) : "l"(p));
    return a;
}
__device__ __forceinline__ float fast_tanh(float v) {
    float r;
    asm("tanh.approx.f32 %0, %1;" : "=f"(r) : "f"(v));
    return r;
}
#define CP_ASYNC16(dst, src) \
    asm volatile("cp.async.cg.shared.global [%0], [%1], 16;" :: "r"(dst), "l"(src))
#define CP_COMMIT() asm volatile("cp.async.commit_group;" ::: "memory")
#define CP_WAIT(n)  asm volatile("cp.async.wait_group %0;" :: "n"(n) : "memory")

#define LDSM_X4(r, addr)                                                      \
    asm volatile("ldmatrix.sync.aligned.m8n8.x4.shared.b16 {%0,%1,%2,%3}, [%4];" \
                 : "=r"((r)[0]), "=r"((r)[1]), "=r"((r)[2]), "=r"((r)[3]) : "r"(addr))

#define MMA16816F16(c, a, b0, b1)                                             \
    asm volatile("mma.sync.aligned.m16n8k16.row.col.f32.f16.f16.f32 "         \
                 "{%0,%1,%2,%3}, {%4,%5,%6,%7}, {%8,%9}, {%0,%1,%2,%3};"      \
                 : "+f"((c)[0]), "+f"((c)[1]), "+f"((c)[2]), "+f"((c)[3])     \
                 : "r"((a)[0]), "r"((a)[1]), "r"((a)[2]), "r"((a)[3]),        \
                   "r"(b0), "r"(b1))

// ---------------------------------------------------------------- fused prep
// blocks [0,128):    W pack -> fp16 (2 o-rows per block, smem staged)
// blocks [128,640):  A features -> fp16 (2 b-rows per block, smem staged)
// blocks [640,896):  out = bias (float4)
__global__ void prep_kernel(const float* __restrict__ x,
                            const float* __restrict__ grid,
                            const float* __restrict__ coef,
                            const float* __restrict__ scale_sp,
                            const float* __restrict__ scale_base,
                            const float* __restrict__ bias_w,
                            float* __restrict__ out) {
    __shared__ __align__(16) __half sh[2 * KDIM];   // 4608B

    const int blk = blockIdx.x;
    const int tid = threadIdx.x;

    if (blk >= 640) {                        // bias init
        int idx = (blk - 640) * 256 + tid;   // float4 units
        float4 v = reinterpret_cast<const float4*>(bias_w)[idx & 63];
        reinterpret_cast<float4*>(out)[idx] = v;
        return;
    }

    float vals[KF];
    __half* gdst;

    if (blk < 128) {                         // ---- W pack (fp16)
        int n = blk * 256 + tid;             // o*128 + i
        float sp = scale_sp[n];
        float4 c0 = reinterpret_cast<const float4*>(coef + (size_t)n * NUM_F)[0];
        float4 c1 = reinterpret_cast<const float4*>(coef + (size_t)n * NUM_F)[1];
        vals[0] = c0.x * sp; vals[1] = c0.y * sp; vals[2] = c0.z * sp; vals[3] = c0.w * sp;
        vals[4] = c1.x * sp; vals[5] = c1.y * sp; vals[6] = c1.z * sp; vals[7] = c1.w * sp;
        vals[8] = scale_base[n];
        gdst = g_W + (size_t)blk * 2 * KDIM;
    } else {                                 // ---- A features
        int idx = (blk - 128) * 256 + tid;   // b*128 + i
        float xv = x[idx];
        // sin(k*x), k=1..8 via Chebyshev recurrence: 2 MUFU
        float s1  = __sinf(xv);
        float c1v = __cosf(xv);
        float two_c = 2.0f * c1v;
        float sm1 = 0.0f, sk = s1;
        vals[0] = s1;
        #pragma unroll
        for (int f = 1; f < NUM_F; f++) {
            float sn = two_c * sk - sm1;
            vals[f] = sn;
            sm1 = sk;
            sk = sn;
        }
        // silu(x) = x * 0.5*(1 + tanh(x/2)): 1 MUFU
        vals[NUM_F] = xv * 0.5f * (1.0f + fast_tanh(0.5f * xv));
        gdst = g_A + (size_t)(blk - 128) * 2 * KDIM;
    }

    // stage into smem (local row = tid>>7, col = (tid&127)*9), coalesced flush
    {
        int lofs = (tid >> 7) * KDIM + (tid & 127) * KF;
        #pragma unroll
        for (int f = 0; f < KF; f++) sh[lofs + f] = __float2half(vals[f]);
    }
    __syncthreads();
    for (int u = tid; u < 288; u += 256)
        reinterpret_cast<uint4*>(gdst)[u] = reinterpret_cast<const uint4*>(sh)[u];
}

// ---------------------------------------------------------------- GEMM
// grid (16, 4, 5) = 320 CTAs (~2.2/SM, 64KB smem -> up to 3 resident).
// 128 threads, 4 warps (2x2), warp tile 32x32, 8 independent MMAs per kstep.
// PREFETCH-ALL: all k-chunks issued as cp.async groups up front; drain with
// compile-time wait counts.  z-chunks 4/4/4/3/3.
// Epilogue RED.ADD into out (bias prewritten by prep).
__global__ __launch_bounds__(128) void gemm_kernel(float* __restrict__ out) {
    extern __shared__ __align__(128) uint8_t smem[];

    const int tid = threadIdx.x;
    const int wid = tid >> 5;
    const int lid = tid & 31;
    const int wm  = wid >> 1;          // 0..1 -> m rows wm*32
    const int wn  = wid & 1;           // 0..1 -> n cols wn*32
    const int m0  = blockIdx.x * TILE_M;
    const int n0  = blockIdx.y * TILE_N;
    const int z   = blockIdx.z;

    const int c0     = (z < 3) ? z * 4 : 12 + (z - 3) * 3;
    const int scount = (z < 3) ? 4 : 3;

    const uint32_t smbase = smem_u32(smem);

    // ldmatrix addressing (proven pattern, warp tile 32x32)
    const uint32_t swz   = (uint32_t)((lid & 7) * 16);
    const uint32_t acol  = (uint32_t)((lid >> 4) * 16);
    const uint32_t arow0 = (uint32_t)((wm * 32 + (lid & 15)) * 128);
    const uint32_t arow1 = arow0 + 16 * 128;
    const uint32_t bcol  = (uint32_t)(((lid >> 3) & 1) * 16);
    const uint32_t brow0 = (uint32_t)((wn * 32 + (lid >> 4) * 8 + (lid & 7)) * 128);
    const uint32_t brow1 = brow0 + 16 * 128;

    float acc[2][4][4];
    #pragma unroll
    for (int j = 0; j < 2; j++)
        #pragma unroll
        for (int q = 0; q < 4; q++)
            #pragma unroll
            for (int r = 0; r < 4; r++) acc[j][q][r] = 0.0f;

    // loader: per stage 1024 x 16B -> 8 cp.async per thread (4 A + 4 W rows)
    const int lrow = tid >> 3;                       // 0..15
    const int lc16 = tid & 7;
    const uint32_t lswz = (uint32_t)((lc16 * 16) ^ ((lrow & 7) * 16));

    auto issue_stage = [&](int s) {
        const int kofs = (c0 + s) * BK + lc16 * 8;
        const uint32_t sb = smbase + s * STAGE_BYTES;
        #pragma unroll
        for (int t = 0; t < 4; t++) {
            const int row = lrow + t * 16;
            const uint32_t rb = (uint32_t)(row * 128) + lswz;
            CP_ASYNC16(sb + rb,        g_A + (size_t)(m0 + row) * KDIM + kofs);
            CP_ASYNC16(sb + 8192 + rb, g_W + (size_t)(n0 + row) * KDIM + kofs);
        }
        CP_COMMIT();
    };

    // issue ALL stages up front
    for (int s = 0; s < scount; s++) issue_stage(s);

    auto compute_chunk = [&](int s) {
        const uint32_t sb  = smbase + s * STAGE_BYTES;
        const uint32_t sbW = sb + 8192;
        #pragma unroll
        for (int kb2 = 0; kb2 < 128; kb2 += 32) {     // 4 k16 steps (bytes)
            const uint32_t ka = ((uint32_t)kb2 + acol) ^ swz;
            const uint32_t kb = ((uint32_t)kb2 + bcol) ^ swz;
            uint32_t a0[4], a1[4], w0[4], w1[4];
            LDSM_X4(a0, sb + arow0 + ka);
            LDSM_X4(a1, sb + arow1 + ka);
            LDSM_X4(w0, sbW + brow0 + kb);
            LDSM_X4(w1, sbW + brow1 + kb);
            // 8 independent MMAs
            MMA16816F16(acc[0][0], a0, w0[0], w0[1]);
            MMA16816F16(acc[0][1], a0, w0[2], w0[3]);
            MMA16816F16(acc[0][2], a0, w1[0], w1[1]);
            MMA16816F16(acc[0][3], a0, w1[2], w1[3]);
            MMA16816F16(acc[1][0], a1, w0[0], w0[1]);
            MMA16816F16(acc[1][1], a1, w0[2], w0[3]);
            MMA16816F16(acc[1][2], a1, w1[0], w1[1]);
            MMA16816F16(acc[1][3], a1, w1[2], w1[3]);
        }
    };

    // drain with compile-time wait counts (groups complete in commit order)
    if (scount == 4) {
        CP_WAIT(3); __syncthreads(); compute_chunk(0);
        CP_WAIT(2); __syncthreads(); compute_chunk(1);
        CP_WAIT(1); __syncthreads(); compute_chunk(2);
        CP_WAIT(0); __syncthreads(); compute_chunk(3);
    } else {
        CP_WAIT(2); __syncthreads(); compute_chunk(0);
        CP_WAIT(1); __syncthreads(); compute_chunk(1);
        CP_WAIT(0); __syncthreads(); compute_chunk(2);
    }

    // epilogue: RED.ADD into out (bias already written by prep)
    #pragma unroll
    for (int j = 0; j < 2; j++) {
        int r = m0 + wm * 32 + j * 16 + (lid >> 2);
        #pragma unroll
        for (int q = 0; q < 4; q++) {
            int c = n0 + wn * 32 + q * 8 + (lid & 3) * 2;
            float* p = out + (size_t)r * OUT_DIM + c;
            atomicAdd(p,                    acc[j][q][0]);
            atomicAdd(p + 1,                acc[j][q][1]);
            atomicAdd(p + 8 * OUT_DIM,      acc[j][q][2]);
            atomicAdd(p + 8 * OUT_DIM + 1,  acc[j][q][3]);
        }
    }
}

// ---------------------------------------------------------------- launch
extern "C" void kernel_launch(void* const* d_in, const int* in_sizes, int n_in,
                              void* d_out, int out_size) {
    const float* x          = (const float*)d_in[0];
    const float* grid       = (const float*)d_in[1];
    const float* coef       = (const float*)d_in[2];
    const float* scale_sp   = (const float*)d_in[3];
    const float* scale_base = (const float*)d_in[4];
    const float* bias_w     = (const float*)d_in[5];
    float* out = (float*)d_out;

    cudaFuncSetAttribute(gemm_kernel, cudaFuncAttributeMaxDynamicSharedMemorySize,
                         SMEM_BYTES);

    prep_kernel<<<896, 256>>>(x, grid, coef, scale_sp, scale_base, bias_w, out);

    dim3 gdim(BATCH / TILE_M, OUT_DIM / TILE_N, ZSPLIT);   // (16, 4, 5) = 320 CTAs
    gemm_kernel<<<gdim, 128, SMEM_BYTES>>>(out);
}